// round 10
// baseline (speedup 1.0000x reference)
#include <cuda_runtime.h>
#include <math.h>

// ---------------------------------------------------------------------------
// R10: halo-split fused KAN generator.
//   prep_weights  <<<24,256>>> : build tap-combined weights for all 4 stages
//                                once into g_wsh (removes per-block rebuild).
//   fused_kan     <<<1024,256>>>: TWO blocks per sample; block computes output
//                                rows [16h,16h+16). Backward dependency:
//     stage1 (4x4)  : full           stage2 (8x8)  : full
//     stage3 (16x16): rows [0,10) / [6,16)   (Y in [0,5) / [3,8))
//     stage4 (32x32): rows [16h,16h+16)      (Y in [8h,8h+8))
//   ~15% redundant early-stage work buys 2x grid -> 40 warps/SM (was 27.7).
// Phase C = R6 dense form: haloed feature arrays (border = spline(0) feats),
// broadcast weight LDS, conflict-free float4/float2 feature LDS.
// ---------------------------------------------------------------------------

#define F0A make_float4(0.0f, 0.125f, 0.75f, 0.125f)
#define F0B make_float2(0.0f, 0.0f)

__device__ float4 g_wsh[4 * 384];   // [stage][ (p,pos,c,f) ] -> float4 over co

__device__ __forceinline__ void spline_feats(float v, float4& fa, float2& fb) {
    const float H = 2.0f / 3.0f;
    float g[8];
#pragma unroll
    for (int i = 0; i < 8; i++) g[i] = (float)(i - 2) * H - 1.0f;
    float b0[7];
#pragma unroll
    for (int i = 0; i < 7; i++)
        b0[i] = (v >= g[i] && v < g[i + 1]) ? 1.0f : 0.0f;
    float b1[6];
#pragma unroll
    for (int i = 0; i < 6; i++)
        b1[i] = (v - g[i]) * (1.0f / (g[i + 1] - g[i])) * b0[i]
              + (g[i + 2] - v) * (1.0f / (g[i + 2] - g[i + 1])) * b0[i + 1];
    float b2[5];
#pragma unroll
    for (int i = 0; i < 5; i++)
        b2[i] = (v - g[i]) * (1.0f / (g[i + 2] - g[i])) * b1[i]
              + (g[i + 3] - v) * (1.0f / (g[i + 3] - g[i + 1])) * b1[i + 1];
    fa = make_float4(b2[0], b2[1], b2[2], b2[3]);
    fb = make_float2(b2[4], fmaxf(v, 0.0f));
}

template <int COUT>
__device__ __forceinline__ void fmaC(float s, float4 w, float4& a) {
    a.x = fmaf(s, w.x, a.x);
    a.y = fmaf(s, w.y, a.y);
    a.z = fmaf(s, w.z, a.z);
    if (COUT == 4) a.w = fmaf(s, w.w, a.w);
}

// ----------------------------- prep kernel ---------------------------------
__global__ void prep_weights(
    const float* __restrict__ bw1, const float* __restrict__ sw1,
    const float* __restrict__ bw2, const float* __restrict__ sw2,
    const float* __restrict__ bw3, const float* __restrict__ sw3,
    const float* __restrict__ bw4, const float* __restrict__ sw4)
{
    int idx = blockIdx.x * 256 + threadIdx.x;
    if (idx >= 4 * 1536) return;
    int s = idx / 1536, e = idx % 1536;
    const float* bw = (s == 0) ? bw1 : (s == 1) ? bw2 : (s == 2) ? bw3 : bw4;
    const float* sw = (s == 0) ? sw1 : (s == 1) ? sw2 : (s == 2) ? sw3 : sw4;
    const int COUT = (s == 3) ? 3 : 4;

    int co  = e & 3;
    int wf  = (e >> 2) % 6;
    int c   = (e / 24) & 3;
    int pos = (e / 96) & 3;
    int p   = e / 384;
    int py = p >> 1, px = p & 1;
    int ry = pos >> 1, rx = pos & 1;
    float val = 0.0f;
    if (co < COUT) {
        int ky0 = ry * (1 + py), nky = 1 + (ry ^ py);
        int kx0 = rx * (1 + px), nkx = 1 + (rx ^ px);
        for (int a = 0; a < nky; a++)
            for (int bb = 0; bb < nkx; bb++) {
                int j = c * 9 + (ky0 + a) * 3 + (kx0 + bb);
                val += (wf == 5) ? bw[co * 36 + j]
                                 : sw[(co * 36 + j) * 5 + wf];
            }
    }
    reinterpret_cast<float*>(g_wsh)[idx] = val;
}

// ----------------------------- one conv stage ------------------------------
// YR rows of Y starting at Y0; featurize NR source rows starting at FR0.
template <int HIN, int COUT, bool FINAL, int YR, int NR>
__device__ __forceinline__ void do_stage(
    const float4* __restrict__ gw, int Y0, int FR0,
    float* act, float4* featA, float2* featB, float4* wsh4, float* gout)
{
    constexpr int S2   = HIN * HIN;
    constexpr int HOUT = 2 * HIN;
    constexpr int HP   = HIN + 2;
    constexpr int S2P  = HP * HP;
    constexpr int TOT  = YR * HIN;            // pixels per parity group
    constexpr int NPX  = (TOT + 63) / 64;
    constexpr int JSTR = (HIN >= 8) ? 64 / HIN : 1;
    const int tid = threadIdx.x;

    // --- copy combined weights from global (L2/L1-hot, built by prep kernel)
#pragma unroll
    for (int k = 0; k < 2; k++) {
        int i = tid + k * 256;
        if (i < 384) wsh4[i] = __ldg(gw + i);
    }

    // --- border ring: spline(0) features (zero-padding contribution)
    {
        constexpr int NB = 2 * HP + 2 * HIN;
        for (int e = tid; e < 4 * NB; e += 256) {
            int c = e / NB, r = e % NB;
            int y, x;
            if (r < 2 * HP) { y = (r < HP) ? 0 : HP - 1; x = (r < HP) ? r : r - HP; }
            else { int r2 = r - 2 * HP;
                   y = 1 + ((r2 < HIN) ? r2 : r2 - HIN);
                   x = (r2 < HIN) ? 0 : HP - 1; }
            int slot = c * S2P + y * HP + x;
            featA[slot] = F0A;
            featB[slot] = F0B;
        }
    }

    // --- featurize source rows [FR0, FR0+NR)
    constexpr int FTOT = 4 * NR * HIN;
#pragma unroll
    for (int k = 0; k < (FTOT + 255) / 256; k++) {
        int lv = tid + k * 256;
        if ((FTOT % 256 == 0) || lv < FTOT) {
            int c   = lv / (NR * HIN);
            int rem = lv - c * (NR * HIN);
            int r   = rem / HIN, xx = rem % HIN;
            int y   = FR0 + r;
            float4 fa; float2 fb;
            spline_feats(act[c * S2 + y * HIN + xx], fa, fb);
            int slot = c * S2P + (y + 1) * HP + (xx + 1);
            featA[slot] = fa;
            featB[slot] = fb;
        }
    }
    __syncthreads();

    // --- phase C
    const int p  = tid >> 6;       // warp-uniform parity
    const int l  = tid & 63;
    const int py = p >> 1, px = p & 1;

    if (NPX > 1 || l < TOT) {
        const int X  = l % HIN;
        const int Yb = Y0 + l / HIN;          // pixel j has Y = Yb + j*JSTR
        const int base = (Yb + py) * HP + X + px;

        float4 acc[NPX];
#pragma unroll
        for (int j = 0; j < NPX; j++) acc[j] = make_float4(0.f, 0.f, 0.f, 0.f);

#pragma unroll
        for (int pos = 0; pos < 4; pos++) {
            const int ry = pos >> 1, rx = pos & 1;
            const float4* wp = wsh4 + (p * 4 + pos) * 24;
#pragma unroll
            for (int c = 0; c < 4; c++) {
                const int off = base + c * S2P + ry * HP + rx;
                float4 fa[NPX];
                float2 fb[NPX];
#pragma unroll
                for (int j = 0; j < NPX; j++) {
                    fa[j] = featA[off + j * JSTR * HP];
                    fb[j] = featB[off + j * JSTR * HP];
                }
                const float4* w = wp + c * 6;
#pragma unroll
                for (int f = 0; f < 6; f++) {
                    float4 wv = w[f];
#pragma unroll
                    for (int j = 0; j < NPX; j++) {
                        float s = (f == 0) ? fa[j].x : (f == 1) ? fa[j].y
                                : (f == 2) ? fa[j].z : (f == 3) ? fa[j].w
                                : (f == 4) ? fb[j].x : fb[j].y;
                        fmaC<COUT>(s, wv, acc[j]);
                    }
                }
            }
        }

        // --- write outputs (absolute rows)
#pragma unroll
        for (int j = 0; j < NPX; j++) {
            int Y = Yb + j * JSTR;
            int y = 2 * Y + py, x = 2 * X + px;
            if (FINAL) {
                gout[0 * HOUT * HOUT + y * HOUT + x] = tanhf(acc[j].x);
                gout[1 * HOUT * HOUT + y * HOUT + x] = tanhf(acc[j].y);
                gout[2 * HOUT * HOUT + y * HOUT + x] = tanhf(acc[j].z);
            } else {
                act[0 * HOUT * HOUT + y * HOUT + x] = acc[j].x;
                act[1 * HOUT * HOUT + y * HOUT + x] = acc[j].y;
                act[2 * HOUT * HOUT + y * HOUT + x] = acc[j].z;
                act[3 * HOUT * HOUT + y * HOUT + x] = acc[j].w;
            }
        }
    }
    __syncthreads();
}

// ----------------------------- fused kernel --------------------------------
__global__ void __launch_bounds__(256, 5) fused_kan_kernel(
    const float* __restrict__ x,
    const float* __restrict__ lin_w,
    const float* __restrict__ lin_b,
    float* __restrict__ out)
{
    __shared__ float  act[1024];
    __shared__ float4 featA[4 * 18 * 18];
    __shared__ float2 featB[4 * 18 * 18];
    __shared__ float4 wsh4[384];

    const int tid = threadIdx.x;
    const int b   = blockIdx.x >> 1;
    const int h   = blockIdx.x & 1;

    // linear + relu: 16 outputs, 4 threads each over 25-element chunks
    if (tid < 64) {
        int j = tid >> 2, qp = tid & 3;
        const float* xr = x + b * 100 + qp * 25;
        const float* wr = lin_w + j * 100 + qp * 25;
        float acc = 0.0f;
#pragma unroll
        for (int i = 0; i < 25; i++) acc = fmaf(xr[i], wr[i], acc);
        acc += __shfl_xor_sync(0xffffffffu, acc, 1);
        acc += __shfl_xor_sync(0xffffffffu, acc, 2);
        if (qp == 0) act[j] = fmaxf(acc + lin_b[j], 0.0f);
    }
    __syncthreads();

    // stage1: full.  stage2: full.
    // stage3: Y in [3h, 3h+5)  -> rows [6h, 6h+10)
    // stage4: Y in [8h, 8h+8)  -> rows [16h, 16h+16); featurize rows [6h,6h+10)
    do_stage<2, 4, false, 2, 2>  (g_wsh,        0,     0,     act, featA, featB, wsh4, nullptr);
    do_stage<4, 4, false, 4, 4>  (g_wsh + 384,  0,     0,     act, featA, featB, wsh4, nullptr);
    do_stage<8, 4, false, 5, 8>  (g_wsh + 768,  3 * h, 0,     act, featA, featB, wsh4, nullptr);
    do_stage<16, 3, true, 8, 10> (g_wsh + 1152, 8 * h, 6 * h, act, featA, featB, wsh4,
                                  out + (size_t)b * 3 * 32 * 32);
}

// ---------------------------------------------------------------------------
extern "C" void kernel_launch(void* const* d_in, const int* in_sizes, int n_in,
                              void* d_out, int out_size) {
    const float* x     = (const float*)d_in[0];
    const float* lin_w = (const float*)d_in[1];
    const float* lin_b = (const float*)d_in[2];
    const float* bw1   = (const float*)d_in[3];
    const float* sw1   = (const float*)d_in[4];
    const float* bw2   = (const float*)d_in[5];
    const float* sw2   = (const float*)d_in[6];
    const float* bw3   = (const float*)d_in[7];
    const float* sw3   = (const float*)d_in[8];
    const float* bw4   = (const float*)d_in[9];
    const float* sw4   = (const float*)d_in[10];

    prep_weights<<<24, 256>>>(bw1, sw1, bw2, sw2, bw3, sw3, bw4, sw4);
    fused_kan_kernel<<<1024, 256>>>(x, lin_w, lin_b, (float*)d_out);
}

// round 11
// speedup vs baseline: 1.3122x; 1.3122x over previous
#include <cuda_runtime.h>
#include <math.h>

// ---------------------------------------------------------------------------
// R11: fused KAN generator, 512 blocks (one clean wave) x 256 threads,
// one sample per block; weights tap-combined ONCE by a prep kernel.
//   prep_weights <<<24,256>>> : builds g_wsh[stage][(p,pos,c,f)]->float4 co
//   fused_kan    <<<512,256>>>: 4 stages in SMEM, haloed features
// Phase C: parity p = tid>>6 warp-uniform; 64-lane group covers S2 pixels,
// NPX = S2/64 strided pixels/thread; weight float4 broadcast once per NPX px;
// haloed feature arrays (border ring = spline(0) feats) -> no bounds checks.
// Stage 4 COUT=3-specialized; final tanh via __expf (validated 6e-7 rel_err).
// ---------------------------------------------------------------------------

#define F0A make_float4(0.0f, 0.125f, 0.75f, 0.125f)
#define F0B make_float2(0.0f, 0.0f)

__device__ float4 g_wsh[4 * 384];

__device__ __forceinline__ float ftanh(float x) {
    float e = __expf(2.0f * x);
    return 1.0f - __fdividef(2.0f, e + 1.0f);
}

__device__ __forceinline__ void spline_feats(float v, float4& fa, float2& fb) {
    const float H = 2.0f / 3.0f;
    float g[8];
#pragma unroll
    for (int i = 0; i < 8; i++) g[i] = (float)(i - 2) * H - 1.0f;
    float b0[7];
#pragma unroll
    for (int i = 0; i < 7; i++)
        b0[i] = (v >= g[i] && v < g[i + 1]) ? 1.0f : 0.0f;
    float b1[6];
#pragma unroll
    for (int i = 0; i < 6; i++)
        b1[i] = (v - g[i]) * (1.0f / (g[i + 1] - g[i])) * b0[i]
              + (g[i + 2] - v) * (1.0f / (g[i + 2] - g[i + 1])) * b0[i + 1];
    float b2[5];
#pragma unroll
    for (int i = 0; i < 5; i++)
        b2[i] = (v - g[i]) * (1.0f / (g[i + 2] - g[i])) * b1[i]
              + (g[i + 3] - v) * (1.0f / (g[i + 3] - g[i + 1])) * b1[i + 1];
    fa = make_float4(b2[0], b2[1], b2[2], b2[3]);
    fb = make_float2(b2[4], fmaxf(v, 0.0f));
}

template <int COUT>
__device__ __forceinline__ void fmaC(float s, float4 w, float4& a) {
    a.x = fmaf(s, w.x, a.x);
    a.y = fmaf(s, w.y, a.y);
    a.z = fmaf(s, w.z, a.z);
    if (COUT == 4) a.w = fmaf(s, w.w, a.w);
}

// ----------------------------- prep kernel ---------------------------------
__global__ void prep_weights(
    const float* __restrict__ bw1, const float* __restrict__ sw1,
    const float* __restrict__ bw2, const float* __restrict__ sw2,
    const float* __restrict__ bw3, const float* __restrict__ sw3,
    const float* __restrict__ bw4, const float* __restrict__ sw4)
{
    int idx = blockIdx.x * 256 + threadIdx.x;
    if (idx >= 4 * 1536) return;
    int s = idx / 1536, e = idx % 1536;
    const float* bw = (s == 0) ? bw1 : (s == 1) ? bw2 : (s == 2) ? bw3 : bw4;
    const float* sw = (s == 0) ? sw1 : (s == 1) ? sw2 : (s == 2) ? sw3 : sw4;
    const int COUT = (s == 3) ? 3 : 4;

    int co  = e & 3;
    int wf  = (e >> 2) % 6;
    int c   = (e / 24) & 3;
    int pos = (e / 96) & 3;
    int p   = e / 384;
    int py = p >> 1, px = p & 1;
    int ry = pos >> 1, rx = pos & 1;
    float val = 0.0f;
    if (co < COUT) {
        int ky0 = ry * (1 + py), nky = 1 + (ry ^ py);
        int kx0 = rx * (1 + px), nkx = 1 + (rx ^ px);
        for (int a = 0; a < nky; a++)
            for (int bb = 0; bb < nkx; bb++) {
                int j = c * 9 + (ky0 + a) * 3 + (kx0 + bb);
                val += (wf == 5) ? bw[co * 36 + j]
                                 : sw[(co * 36 + j) * 5 + wf];
            }
    }
    reinterpret_cast<float*>(g_wsh)[idx] = val;
}

// ----------------------------- one conv stage ------------------------------
template <int HIN, int COUT, bool FINAL>
__device__ __forceinline__ void do_stage(
    const float4* __restrict__ gw,
    float* act, float4* featA, float2* featB, float4* wsh4, float* gout)
{
    constexpr int S2   = HIN * HIN;
    constexpr int NSRC = 4 * S2;
    constexpr int HOUT = 2 * HIN;
    constexpr int HP   = HIN + 2;
    constexpr int S2P  = HP * HP;
    constexpr int NPX  = (S2 > 64) ? S2 / 64 : 1;
    constexpr int JSTR = (HIN >= 8) ? 64 / HIN : 1;
    const int tid = threadIdx.x;

    // --- copy combined weights from global (coalesced, L2-hot)
#pragma unroll
    for (int k = 0; k < 2; k++) {
        int i = tid + k * 256;
        if (i < 384) wsh4[i] = __ldg(gw + i);
    }

    // --- border ring: spline(0) features (zero-padding contribution)
    {
        constexpr int NB = 2 * HP + 2 * HIN;
        for (int e = tid; e < 4 * NB; e += 256) {
            int c = e / NB, r = e % NB;
            int y, x;
            if (r < 2 * HP) { y = (r < HP) ? 0 : HP - 1; x = (r < HP) ? r : r - HP; }
            else { int r2 = r - 2 * HP;
                   y = 1 + ((r2 < HIN) ? r2 : r2 - HIN);
                   x = (r2 < HIN) ? 0 : HP - 1; }
            int slot = c * S2P + y * HP + x;
            featA[slot] = F0A;
            featB[slot] = F0B;
        }
    }

    // --- featurize interior source values
#pragma unroll
    for (int k = 0; k < (NSRC + 255) / 256; k++) {
        int lv = tid + k * 256;
        if (NSRC >= 256 || lv < NSRC) {
            int c = lv / S2, rem = lv % S2;
            int y = rem / HIN, x = rem % HIN;
            float4 fa; float2 fb;
            spline_feats(act[lv], fa, fb);
            int slot = c * S2P + (y + 1) * HP + (x + 1);
            featA[slot] = fa;
            featB[slot] = fb;
        }
    }
    __syncthreads();

    // --- phase C: pure LDS+FFMA
    const int p  = tid >> 6;       // warp-uniform parity
    const int l  = tid & 63;
    const int py = p >> 1, px = p & 1;

    if (S2 >= 64 || l < S2) {
        const int Yb = l / HIN;
        const int X  = l % HIN;
        const int base = (Yb + py) * HP + X + px;

        float4 acc[NPX];
#pragma unroll
        for (int j = 0; j < NPX; j++) acc[j] = make_float4(0.f, 0.f, 0.f, 0.f);

#pragma unroll
        for (int pos = 0; pos < 4; pos++) {
            const int ry = pos >> 1, rx = pos & 1;
            const float4* wp = wsh4 + (p * 4 + pos) * 24;
#pragma unroll
            for (int c = 0; c < 4; c++) {
                const int off = base + c * S2P + ry * HP + rx;
                float4 fa[NPX];
                float2 fb[NPX];
#pragma unroll
                for (int j = 0; j < NPX; j++) {
                    fa[j] = featA[off + j * JSTR * HP];
                    fb[j] = featB[off + j * JSTR * HP];
                }
                const float4* w = wp + c * 6;
#pragma unroll
                for (int f = 0; f < 6; f++) {
                    float4 wv = w[f];
#pragma unroll
                    for (int j = 0; j < NPX; j++) {
                        float s = (f == 0) ? fa[j].x : (f == 1) ? fa[j].y
                                : (f == 2) ? fa[j].z : (f == 3) ? fa[j].w
                                : (f == 4) ? fb[j].x : fb[j].y;
                        fmaC<COUT>(s, wv, acc[j]);
                    }
                }
            }
        }

        // --- write outputs
#pragma unroll
        for (int j = 0; j < NPX; j++) {
            int Y = Yb + j * JSTR;
            int y = 2 * Y + py, x = 2 * X + px;
            if (FINAL) {
                gout[0 * HOUT * HOUT + y * HOUT + x] = ftanh(acc[j].x);
                gout[1 * HOUT * HOUT + y * HOUT + x] = ftanh(acc[j].y);
                gout[2 * HOUT * HOUT + y * HOUT + x] = ftanh(acc[j].z);
            } else {
                act[0 * HOUT * HOUT + y * HOUT + x] = acc[j].x;
                act[1 * HOUT * HOUT + y * HOUT + x] = acc[j].y;
                act[2 * HOUT * HOUT + y * HOUT + x] = acc[j].z;
                act[3 * HOUT * HOUT + y * HOUT + x] = acc[j].w;
            }
        }
    }
    __syncthreads();
}

// ----------------------------- fused kernel --------------------------------
__global__ void __launch_bounds__(256, 4) fused_kan_kernel(
    const float* __restrict__ x,
    const float* __restrict__ lin_w,
    const float* __restrict__ lin_b,
    float* __restrict__ out)
{
    __shared__ float  act[1024];
    __shared__ float4 featA[4 * 18 * 18];
    __shared__ float2 featB[4 * 18 * 18];
    __shared__ float4 wsh4[384];

    const int tid = threadIdx.x;
    const int b   = blockIdx.x;

    // linear + relu: 16 outputs, 4 threads each over 25-element chunks
    if (tid < 64) {
        int j = tid >> 2, qp = tid & 3;
        const float* xr = x + b * 100 + qp * 25;
        const float* wr = lin_w + j * 100 + qp * 25;
        float acc = 0.0f;
#pragma unroll
        for (int i = 0; i < 25; i++) acc = fmaf(xr[i], wr[i], acc);
        acc += __shfl_xor_sync(0xffffffffu, acc, 1);
        acc += __shfl_xor_sync(0xffffffffu, acc, 2);
        if (qp == 0) act[j] = fmaxf(acc + lin_b[j], 0.0f);
    }
    __syncthreads();

    do_stage<2, 4, false>(g_wsh,        act, featA, featB, wsh4, nullptr);
    do_stage<4, 4, false>(g_wsh + 384,  act, featA, featB, wsh4, nullptr);
    do_stage<8, 4, false>(g_wsh + 768,  act, featA, featB, wsh4, nullptr);
    do_stage<16, 3, true>(g_wsh + 1152, act, featA, featB, wsh4,
                          out + (size_t)b * 3 * 32 * 32);
}

// ---------------------------------------------------------------------------
extern "C" void kernel_launch(void* const* d_in, const int* in_sizes, int n_in,
                              void* d_out, int out_size) {
    const float* x     = (const float*)d_in[0];
    const float* lin_w = (const float*)d_in[1];
    const float* lin_b = (const float*)d_in[2];
    const float* bw1   = (const float*)d_in[3];
    const float* sw1   = (const float*)d_in[4];
    const float* bw2   = (const float*)d_in[5];
    const float* sw2   = (const float*)d_in[6];
    const float* bw3   = (const float*)d_in[7];
    const float* sw3   = (const float*)d_in[8];
    const float* bw4   = (const float*)d_in[9];
    const float* sw4   = (const float*)d_in[10];

    prep_weights<<<24, 256>>>(bw1, sw1, bw2, sw2, bw3, sw3, bw4, sw4);
    fused_kan_kernel<<<512, 256>>>(x, lin_w, lin_b, (float*)d_out);
}

// round 13
// speedup vs baseline: 1.3880x; 1.0578x over previous
#include <cuda_runtime.h>
#include <math.h>

// ---------------------------------------------------------------------------
// R12: fused KAN generator, 512 blocks x 256 threads, prep kernel for weights.
// vs R11:
//  * fb=(b4,relu) PAIR-PACKED by row pairs (y, y+POFF) into float4 -> the
//    phase-C j-loop loads half as many fb words (LDS.128 instead of 2x LDS.64)
//  * stage 3 runs NPX=2 (32 active lanes/parity): weight broadcasts halved
// Arithmetic order identical to R11 -> bit-identical results.
// ---------------------------------------------------------------------------

#define F0A make_float4(0.0f, 0.125f, 0.75f, 0.125f)
#define F0B make_float2(0.0f, 0.0f)

__device__ float4 g_wsh[4 * 384];

__device__ __forceinline__ float ftanh(float x) {
    float e = __expf(2.0f * x);
    return 1.0f - __fdividef(2.0f, e + 1.0f);
}

__device__ __forceinline__ void spline_feats(float v, float4& fa, float2& fb) {
    const float H = 2.0f / 3.0f;
    float g[8];
#pragma unroll
    for (int i = 0; i < 8; i++) g[i] = (float)(i - 2) * H - 1.0f;
    float b0[7];
#pragma unroll
    for (int i = 0; i < 7; i++)
        b0[i] = (v >= g[i] && v < g[i + 1]) ? 1.0f : 0.0f;
    float b1[6];
#pragma unroll
    for (int i = 0; i < 6; i++)
        b1[i] = (v - g[i]) * (1.0f / (g[i + 1] - g[i])) * b0[i]
              + (g[i + 2] - v) * (1.0f / (g[i + 2] - g[i + 1])) * b0[i + 1];
    float b2[5];
#pragma unroll
    for (int i = 0; i < 5; i++)
        b2[i] = (v - g[i]) * (1.0f / (g[i + 2] - g[i])) * b1[i]
              + (g[i + 3] - v) * (1.0f / (g[i + 3] - g[i + 1])) * b1[i + 1];
    fa = make_float4(b2[0], b2[1], b2[2], b2[3]);
    fb = make_float2(b2[4], fmaxf(v, 0.0f));
}

template <int COUT>
__device__ __forceinline__ void fmaC(float s, float4 w, float4& a) {
    a.x = fmaf(s, w.x, a.x);
    a.y = fmaf(s, w.y, a.y);
    a.z = fmaf(s, w.z, a.z);
    if (COUT == 4) a.w = fmaf(s, w.w, a.w);
}

// ----------------------------- prep kernel ---------------------------------
__global__ void prep_weights(
    const float* __restrict__ bw1, const float* __restrict__ sw1,
    const float* __restrict__ bw2, const float* __restrict__ sw2,
    const float* __restrict__ bw3, const float* __restrict__ sw3,
    const float* __restrict__ bw4, const float* __restrict__ sw4)
{
    int idx = blockIdx.x * 256 + threadIdx.x;
    if (idx >= 4 * 1536) return;
    int s = idx / 1536, e = idx % 1536;
    const float* bw = (s == 0) ? bw1 : (s == 1) ? bw2 : (s == 2) ? bw3 : bw4;
    const float* sw = (s == 0) ? sw1 : (s == 1) ? sw2 : (s == 2) ? sw3 : sw4;
    const int COUT = (s == 3) ? 3 : 4;

    int co  = e & 3;
    int wf  = (e >> 2) % 6;
    int c   = (e / 24) & 3;
    int pos = (e / 96) & 3;
    int p   = e / 384;
    int py = p >> 1, px = p & 1;
    int ry = pos >> 1, rx = pos & 1;
    float val = 0.0f;
    if (co < COUT) {
        int ky0 = ry * (1 + py), nky = 1 + (ry ^ py);
        int kx0 = rx * (1 + px), nkx = 1 + (rx ^ px);
        for (int a = 0; a < nky; a++)
            for (int bb = 0; bb < nkx; bb++) {
                int j = c * 9 + (ky0 + a) * 3 + (kx0 + bb);
                val += (wf == 5) ? bw[co * 36 + j]
                                 : sw[(co * 36 + j) * 5 + wf];
            }
    }
    reinterpret_cast<float*>(g_wsh)[idx] = val;
}

// ----------------------------- one conv stage ------------------------------
template <int HIN, int COUT, bool FINAL, int NPX>
__device__ __forceinline__ void do_stage(
    const float4* __restrict__ gw,
    float* act, float4* featA, float2* featB, float4* fbP,
    float4* wsh4, float* gout)
{
    constexpr int S2    = HIN * HIN;
    constexpr int NSRC  = 4 * S2;
    constexpr int HOUT  = 2 * HIN;
    constexpr int HP    = HIN + 2;
    constexpr int S2P   = HP * HP;
    constexpr int ACT_L = S2 / NPX;                 // active lanes per parity
    constexpr int JSTR  = (NPX > 1) ? ACT_L / HIN : 1;
    constexpr bool PAIR = (NPX >= 2);
    constexpr int POFF  = PAIR ? (JSTR * NPX / 2) : 1;  // row-pair offset
    constexpr int S2FB  = (HP - POFF) * HP;         // fbP slots per channel
    const int tid = threadIdx.x;

    // --- copy combined weights from global (coalesced, L2-hot)
#pragma unroll
    for (int k = 0; k < 2; k++) {
        int i = tid + k * 256;
        if (i < 384) wsh4[i] = __ldg(gw + i);
    }

    // --- border ring: spline(0) features (zero-padding contribution)
    {
        constexpr int NB = 2 * HP + 2 * HIN;
        for (int e = tid; e < 4 * NB; e += 256) {
            int c = e / NB, r = e % NB;
            int y, x;
            if (r < 2 * HP) { y = (r < HP) ? 0 : HP - 1; x = (r < HP) ? r : r - HP; }
            else { int r2 = r - 2 * HP;
                   y = 1 + ((r2 < HIN) ? r2 : r2 - HIN);
                   x = (r2 < HIN) ? 0 : HP - 1; }
            featA[c * S2P + y * HP + x] = F0A;
            if (PAIR) {
                if (y <= HP - 1 - POFF) {
                    float2* q = reinterpret_cast<float2*>(
                        &fbP[c * S2FB + y * HP + x]);
                    q[0] = F0B;
                }
                if (y >= POFF) {
                    float2* q = reinterpret_cast<float2*>(
                        &fbP[c * S2FB + (y - POFF) * HP + x]);
                    q[1] = F0B;
                }
            } else {
                featB[c * S2P + y * HP + x] = F0B;
            }
        }
    }

    // --- featurize interior source values
#pragma unroll
    for (int k = 0; k < (NSRC + 255) / 256; k++) {
        int lv = tid + k * 256;
        if (NSRC >= 256 || lv < NSRC) {
            int c = lv / S2, rem = lv % S2;
            int y = rem / HIN, x = rem % HIN;
            float4 fa; float2 fb;
            spline_feats(act[lv], fa, fb);
            int yp = y + 1, xp = x + 1;
            featA[c * S2P + yp * HP + xp] = fa;
            if (PAIR) {
                if (yp <= HP - 1 - POFF) {
                    float2* q = reinterpret_cast<float2*>(
                        &fbP[c * S2FB + yp * HP + xp]);
                    q[0] = fb;
                }
                if (yp >= POFF) {
                    float2* q = reinterpret_cast<float2*>(
                        &fbP[c * S2FB + (yp - POFF) * HP + xp]);
                    q[1] = fb;
                }
            } else {
                featB[c * S2P + yp * HP + xp] = fb;
            }
        }
    }
    __syncthreads();

    // --- phase C
    const int p  = tid >> 6;       // warp-uniform parity
    const int l  = tid & 63;
    const int py = p >> 1, px = p & 1;

    if (ACT_L >= 64 || l < ACT_L) {
        const int Yb = l / HIN;
        const int X  = l % HIN;
        const int base = (Yb + py) * HP + X + px;   // fa flat base (sans c)

        float4 acc[NPX];
#pragma unroll
        for (int j = 0; j < NPX; j++) acc[j] = make_float4(0.f, 0.f, 0.f, 0.f);

#pragma unroll
        for (int pos = 0; pos < 4; pos++) {
            const int ry = pos >> 1, rx = pos & 1;
            const float4* wp = wsh4 + (p * 4 + pos) * 24;
#pragma unroll
            for (int c = 0; c < 4; c++) {
                const int off = base + c * S2P + ry * HP + rx;
                float4 fa[NPX];
                float2 fbv[(NPX > 1) ? 1 : NPX];     // only non-PAIR path
                float4 fbQ[(NPX >= 2) ? NPX / 2 : 1];
#pragma unroll
                for (int j = 0; j < NPX; j++)
                    fa[j] = featA[off + j * JSTR * HP];
                if (PAIR) {
                    const int offb = c * S2FB + base + ry * HP + rx;
#pragma unroll
                    for (int k = 0; k < NPX / 2; k++)
                        fbQ[k] = fbP[offb + k * JSTR * HP];
                } else {
                    fbv[0] = featB[off];
                }
                const float4* w = wp + c * 6;
#pragma unroll
                for (int f = 0; f < 6; f++) {
                    float4 wv = w[f];
#pragma unroll
                    for (int j = 0; j < NPX; j++) {
                        float s;
                        if (f < 4) {
                            s = (f == 0) ? fa[j].x : (f == 1) ? fa[j].y
                              : (f == 2) ? fa[j].z : fa[j].w;
                        } else if (PAIR) {
                            s = (j < NPX / 2)
                              ? ((f == 4) ? fbQ[j].x : fbQ[j].y)
                              : ((f == 4) ? fbQ[j - NPX / 2].z
                                          : fbQ[j - NPX / 2].w);
                        } else {
                            s = (f == 4) ? fbv[0].x : fbv[0].y;
                        }
                        fmaC<COUT>(s, wv, acc[j]);
                    }
                }
            }
        }

        // --- write outputs
#pragma unroll
        for (int j = 0; j < NPX; j++) {
            int Y = Yb + j * JSTR;
            int y = 2 * Y + py, x = 2 * X + px;
            if (FINAL) {
                gout[0 * HOUT * HOUT + y * HOUT + x] = ftanh(acc[j].x);
                gout[1 * HOUT * HOUT + y * HOUT + x] = ftanh(acc[j].y);
                gout[2 * HOUT * HOUT + y * HOUT + x] = ftanh(acc[j].z);
            } else {
                act[0 * HOUT * HOUT + y * HOUT + x] = acc[j].x;
                act[1 * HOUT * HOUT + y * HOUT + x] = acc[j].y;
                act[2 * HOUT * HOUT + y * HOUT + x] = acc[j].z;
                act[3 * HOUT * HOUT + y * HOUT + x] = acc[j].w;
            }
        }
    }
    __syncthreads();
}

// ----------------------------- fused kernel --------------------------------
__global__ void __launch_bounds__(256, 4) fused_kan_kernel(
    const float* __restrict__ x,
    const float* __restrict__ lin_w,
    const float* __restrict__ lin_b,
    float* __restrict__ out)
{
    __shared__ float  act[1024];
    __shared__ float4 featA[4 * 18 * 18];   // stage-4 sized, reused
    __shared__ float2 featB[4 * 6 * 6];     // non-pair stages (1,2)
    __shared__ float4 fbP[4 * 10 * 18];     // pair-packed fb (stages 3,4)
    __shared__ float4 wsh4[384];

    const int tid = threadIdx.x;
    const int b   = blockIdx.x;

    // linear + relu: 16 outputs, 4 threads each over 25-element chunks
    if (tid < 64) {
        int j = tid >> 2, qp = tid & 3;
        const float* xr = x + b * 100 + qp * 25;
        const float* wr = lin_w + j * 100 + qp * 25;
        float acc = 0.0f;
#pragma unroll
        for (int i = 0; i < 25; i++) acc = fmaf(xr[i], wr[i], acc);
        acc += __shfl_xor_sync(0xffffffffu, acc, 1);
        acc += __shfl_xor_sync(0xffffffffu, acc, 2);
        if (qp == 0) act[j] = fmaxf(acc + lin_b[j], 0.0f);
    }
    __syncthreads();

    do_stage<2, 4, false, 1>(g_wsh,        act, featA, featB, fbP, wsh4, nullptr);
    do_stage<4, 4, false, 1>(g_wsh + 384,  act, featA, featB, fbP, wsh4, nullptr);
    do_stage<8, 4, false, 2>(g_wsh + 768,  act, featA, featB, fbP, wsh4, nullptr);
    do_stage<16, 3, true, 4>(g_wsh + 1152, act, featA, featB, fbP, wsh4,
                             out + (size_t)b * 3 * 32 * 32);
}

// ---------------------------------------------------------------------------
extern "C" void kernel_launch(void* const* d_in, const int* in_sizes, int n_in,
                              void* d_out, int out_size) {
    const float* x     = (const float*)d_in[0];
    const float* lin_w = (const float*)d_in[1];
    const float* lin_b = (const float*)d_in[2];
    const float* bw1   = (const float*)d_in[3];
    const float* sw1   = (const float*)d_in[4];
    const float* bw2   = (const float*)d_in[5];
    const float* sw2   = (const float*)d_in[6];
    const float* bw3   = (const float*)d_in[7];
    const float* sw3   = (const float*)d_in[8];
    const float* bw4   = (const float*)d_in[9];
    const float* sw4   = (const float*)d_in[10];

    prep_weights<<<24, 256>>>(bw1, sw1, bw2, sw2, bw3, sw3, bw4, sw4);
    fused_kan_kernel<<<512, 256>>>(x, lin_w, lin_b, (float*)d_out);
}